// round 12
// baseline (speedup 1.0000x reference)
#include <cuda_runtime.h>
#include <cstdint>

// B=4, H=256, W=256 torus. mu-subsystem only. Single persistent kernel:
// f32x2 packed (lane = column pair), 128 blocks (1/SM) x 512 thr;
// 16 warps x (5 rows x 64 cols). Region 80r x 64c, interior 64r x 32c,
// T=8, 13 periods (12x8 + 4). Per-iteration sync: pairwise named barriers
// in ODD-EVEN (red-black) order -> 2 parallel stages, no barrier chain.
// Period sync: sense-reversing global barrier (state self-restores after
// 12 uses -> deterministic across graph replays; no init kernel).
#define BHW 262144
#define NBLOCKS 128

typedef unsigned long long ull;

__device__ float g_mu[2][BHW];
__device__ float g_v [2][BHW];
__device__ unsigned g_count;           // zero-init; reset by last arriver
__device__ volatile unsigned g_sense;  // zero-init; flips 12x per run -> returns to 0

// ---------------- packed f32x2 helpers ----------------
__device__ __forceinline__ ull pk(float lo, float hi) {
    ull r; asm("mov.b64 %0, {%1, %2};" : "=l"(r) : "f"(lo), "f"(hi)); return r;
}
__device__ __forceinline__ void upk(ull a, float& lo, float& hi) {
    asm("mov.b64 {%0, %1}, %2;" : "=f"(lo), "=f"(hi) : "l"(a));
}
__device__ __forceinline__ ull fma2(ull a, ull b, ull c) {
    ull d; asm("fma.rn.f32x2 %0, %1, %2, %3;" : "=l"(d) : "l"(a), "l"(b), "l"(c)); return d;
}
__device__ __forceinline__ ull add2(ull a, ull b) {
    ull d; asm("add.rn.f32x2 %0, %1, %2;" : "=l"(d) : "l"(a), "l"(b)); return d;
}
__device__ __forceinline__ ull clip2(ull a) {
    float lo, hi; upk(a, lo, hi);
    lo = fminf(fmaxf(lo, 0.0f), 63.0f);
    hi = fminf(fmaxf(hi, 0.0f), 63.0f);
    return pk(lo, hi);
}

#define K07 0x3F3333333F333333ULL   // (0.7f, 0.7f)

// ---------------- persistent kernel ----------------
__global__ __launch_bounds__(512, 1) void persist_kernel(
        const float* __restrict__ y,
        const float2* __restrict__ ew2,
        const float2* __restrict__ un2,
        float* __restrict__ out) {
    __shared__ ull s_top[2][16][32];     // warp row-0 mu pairs, double-buffered
    __shared__ ull s_bot[2][16][32];     // warp row-4 mu pairs

    const int lane = threadIdx.x & 31;
    const int w    = threadIdx.x >> 5;            // band 0..15 (5 rows each)
    const int blk  = blockIdx.x;                  // 4 img x 4 vtile x 8 htile
    const int base = (blk >> 5) << 16;
    const int tv   = (blk >> 3) & 3;
    const int th   = blk & 7;
    const int gc0  = (th * 32 - 16 + 2 * lane) & 255;   // even; pair never wraps
    const int r0   = tv * 64 - 8 + w * 5;

    // Packed per-row state; constants computed in-prologue from raw inputs
    // (identical arithmetic to the old init kernel). cz2[r] == cx2[r-1].
    ull mu2[5], v2[5], cx2[5], cy2[5], cw2[5], ax2[5], ay2[5], cz0_2;

    #pragma unroll
    for (int r = 0; r < 5; ++r) {
        const int gr = (r0 + r) & 255;
        const int p0 = base + (gr << 8) + gc0;
        const int pL = base + (gr << 8) + ((gc0 + 255) & 255);
        const float y0 = y[p0], y1 = y[p0 + 1];
        mu2[r] = pk(y0, y1);
        v2[r]  = 0ULL;
        const float2 e0 = ew2[p0], e1 = ew2[p0 + 1], el = ew2[pL];
        cx2[r] = pk(0.01f * e0.x, 0.01f * e1.x);
        cy2[r] = pk(0.01f * e0.y, 0.01f * e1.y);
        cw2[r] = pk(0.01f * el.y, 0.01f * e0.y);
        if (r == 0) {
            const int pu = base + (((r0 + 255) & 255) << 8) + gc0;
            const float2 eu0 = ew2[pu], eu1 = ew2[pu + 1];
            cz0_2 = pk(0.01f * eu0.x, 0.01f * eu1.x);
        }
        const float2 u0 = un2[p0], u1 = un2[p0 + 1];
        ax2[r] = pk(0.01f * 2.0f * u0.x, 0.01f * 2.0f * u1.x);
        ay2[r] = pk(0.01f * u0.y * y0,  0.01f * u1.y * y1);
    }
    __syncthreads();

    unsigned local_sense = 0u;

    for (int per = 0; per < 13; ++per) {
        const int TT = (per < 12) ? 8 : 4;

        for (int it = 0; it < TT; ++it) {
            const int rb = it & 1;

            // Publish own old boundary rows for this iteration.
            s_top[rb][w][lane] = mu2[0];
            s_bot[rb][w][lane] = mu2[4];

            // Pairwise named barriers, odd-even scheduled:
            //   barrier id b syncs warps {b-1, b}; warp w joins ids {w, w+1}
            //   (one even, one odd). Stage 1 = all even ids in parallel,
            //   stage 2 = all odd ids. No chain, no accumulated skew.
            if (w & 1) {
                if (w < 15) asm volatile("bar.sync %0, 64;" :: "r"(w + 1) : "memory"); // even id
                asm volatile("bar.sync %0, 64;" :: "r"(w) : "memory");                 // odd id
            } else {
                if (w > 0)  asm volatile("bar.sync %0, 64;" :: "r"(w) : "memory");     // even id
                if (w < 15) asm volatile("bar.sync %0, 64;" :: "r"(w + 1) : "memory"); // odd id
            }

            const ull nb_above = (w > 0)  ? s_bot[rb][w - 1][lane] : mu2[0];
            const ull nb_below = (w < 15) ? s_top[rb][w + 1][lane] : mu2[4];

            ull above = nb_above;
            #pragma unroll
            for (int r = 0; r < 5; ++r) {
                const ull cur   = mu2[r];
                const ull below = (r < 4) ? mu2[r + 1] : nb_below;   // old values
                const ull czr   = (r == 0) ? cz0_2 : cx2[r - 1];
                float clo, chi; upk(cur, clo, chi);
                const float phi = __shfl_up_sync(0xFFFFFFFFu, chi, 1);
                const float nlo = __shfl_down_sync(0xFFFFFFFFu, clo, 1);

                ull dmu = fma2(ax2[r], cur, ay2[r]);
                dmu = fma2(cx2[r], below, dmu);
                dmu = fma2(cy2[r], pk(chi, nlo), dmu);
                dmu = fma2(czr,   above, dmu);
                dmu = fma2(cw2[r], pk(phi, clo), dmu);

                v2[r] = fma2(K07, v2[r], dmu);
                above = cur;
                mu2[r] = clip2(add2(cur, v2[r]));
            }
        }

        const int d = (per + 1) & 1;

        // Write exact interior: region rows 8..71, lanes 8..23 (cols 16..47).
        if (lane >= 8 && lane < 24) {
            #pragma unroll
            for (int r = 0; r < 5; ++r) {
                const int R = w * 5 + r;
                if (R >= 8 && R < 72) {
                    const int p0 = base + (((r0 + r) & 255) << 8) + gc0;
                    *(ull*)&g_mu[d][p0] = mu2[r];
                    *(ull*)&g_v [d][p0] = v2[r];
                    if (per == 12) *(ull*)&out[p0] = mu2[r];
                }
            }
        }

        if (per == 12) break;

        // ---- sense-reversing global period barrier ----
        __threadfence();
        __syncthreads();
        if (threadIdx.x == 0) {
            local_sense ^= 1u;
            const unsigned t = atomicAdd(&g_count, 1u);
            if (t == NBLOCKS - 1) {
                g_count = 0u;                 // reset BEFORE publishing sense
                __threadfence();
                g_sense = local_sense;
            } else {
                while (g_sense != local_sense) { }
            }
            __threadfence();
        }
        __syncthreads();

        // Reload halo cells' mu,v (interior stays in registers).
        #pragma unroll
        for (int r = 0; r < 5; ++r) {
            const int R = w * 5 + r;
            const bool interior = (R >= 8) && (R < 72) && (lane >= 8) && (lane < 24);
            if (!interior) {
                const int p0 = base + (((r0 + r) & 255) << 8) + gc0;
                mu2[r] = *(const ull*)&g_mu[d][p0];
                v2[r]  = *(const ull*)&g_v[d][p0];
            }
        }
        __syncthreads();
    }
}

// ---------------- launch: single persistent kernel ----------------
extern "C" void kernel_launch(void* const* d_in, const int* in_sizes, int n_in,
                              void* d_out, int out_size) {
    const float*  y   = (const float*)d_in[0];
    const float2* ew2 = (const float2*)d_in[1];
    const float2* un2 = (const float2*)d_in[2];
    float* out = (float*)d_out;

    persist_kernel<<<NBLOCKS, 512>>>(y, ew2, un2, out);
}

// round 13
// speedup vs baseline: 1.0901x; 1.0901x over previous
#include <cuda_runtime.h>
#include <cstdint>

// B=4, H=256, W=256 torus. mu-subsystem only. Single persistent kernel:
// f32x2 packed (lane = column pair), 128 blocks (1/SM) x 512 thr;
// 16 warps x (5 rows x 64 cols). Region 80r x 64c, interior 64r x 32c,
// T=8, 13 periods (12x8 + 4).
// Hot-loop sync: R11's pairwise named-barrier CHAIN (measured best).
// Period sync: sense-reversing global barrier (replay-safe, no init kernel).
#define BHW 262144
#define NBLOCKS 128

typedef unsigned long long ull;

__device__ float g_mu[2][BHW];
__device__ float g_v [2][BHW];
__device__ unsigned g_count;           // zero-init; reset by last arriver each use
__device__ volatile unsigned g_sense;  // zero-init; flips 12x per run -> back to 0

// ---------------- packed f32x2 helpers ----------------
__device__ __forceinline__ ull pk(float lo, float hi) {
    ull r; asm("mov.b64 %0, {%1, %2};" : "=l"(r) : "f"(lo), "f"(hi)); return r;
}
__device__ __forceinline__ void upk(ull a, float& lo, float& hi) {
    asm("mov.b64 {%0, %1}, %2;" : "=f"(lo), "=f"(hi) : "l"(a));
}
__device__ __forceinline__ ull fma2(ull a, ull b, ull c) {
    ull d; asm("fma.rn.f32x2 %0, %1, %2, %3;" : "=l"(d) : "l"(a), "l"(b), "l"(c)); return d;
}
__device__ __forceinline__ ull add2(ull a, ull b) {
    ull d; asm("add.rn.f32x2 %0, %1, %2;" : "=l"(d) : "l"(a), "l"(b)); return d;
}
__device__ __forceinline__ ull clip2(ull a) {
    float lo, hi; upk(a, lo, hi);
    lo = fminf(fmaxf(lo, 0.0f), 63.0f);
    hi = fminf(fmaxf(hi, 0.0f), 63.0f);
    return pk(lo, hi);
}

#define K07 0x3F3333333F333333ULL   // (0.7f, 0.7f)

// ---------------- persistent kernel ----------------
__global__ __launch_bounds__(512, 1) void persist_kernel(
        const float* __restrict__ y,
        const float2* __restrict__ ew2,
        const float2* __restrict__ un2,
        float* __restrict__ out) {
    __shared__ ull s_top[2][16][32];     // warp row-0 mu pairs, double-buffered
    __shared__ ull s_bot[2][16][32];     // warp row-4 mu pairs

    const int lane = threadIdx.x & 31;
    const int w    = threadIdx.x >> 5;            // band 0..15 (5 rows each)
    const int blk  = blockIdx.x;                  // 4 img x 4 vtile x 8 htile
    const int base = (blk >> 5) << 16;
    const int tv   = (blk >> 3) & 3;
    const int th   = blk & 7;
    const int gc0  = (th * 32 - 16 + 2 * lane) & 255;   // even; pair never wraps
    const int r0   = tv * 64 - 8 + w * 5;

    // Packed per-row state; constants computed in-prologue from raw inputs
    // (arithmetic identical to the old init kernel). cz2[r] == cx2[r-1].
    ull mu2[5], v2[5], cx2[5], cy2[5], cw2[5], ax2[5], ay2[5], cz0_2;

    #pragma unroll
    for (int r = 0; r < 5; ++r) {
        const int gr = (r0 + r) & 255;
        const int p0 = base + (gr << 8) + gc0;
        const int pL = base + (gr << 8) + ((gc0 + 255) & 255);
        const float y0 = y[p0], y1 = y[p0 + 1];
        mu2[r] = pk(y0, y1);
        v2[r]  = 0ULL;
        const float2 e0 = ew2[p0], e1 = ew2[p0 + 1], el = ew2[pL];
        cx2[r] = pk(0.01f * e0.x, 0.01f * e1.x);
        cy2[r] = pk(0.01f * e0.y, 0.01f * e1.y);
        cw2[r] = pk(0.01f * el.y, 0.01f * e0.y);
        if (r == 0) {
            const int pu = base + (((r0 + 255) & 255) << 8) + gc0;
            const float2 eu0 = ew2[pu], eu1 = ew2[pu + 1];
            cz0_2 = pk(0.01f * eu0.x, 0.01f * eu1.x);
        }
        const float2 u0 = un2[p0], u1 = un2[p0 + 1];
        ax2[r] = pk(0.01f * 2.0f * u0.x, 0.01f * 2.0f * u1.x);
        ay2[r] = pk(0.01f * u0.y * y0,  0.01f * u1.y * y1);
    }
    __syncthreads();

    unsigned local_sense = 0u;

    for (int per = 0; per < 13; ++per) {
        const int TT = (per < 12) ? 8 : 4;

        for (int it = 0; it < TT; ++it) {
            const int rb = it & 1;

            // Publish own old boundary rows for this iteration.
            s_top[rb][w][lane] = mu2[0];
            s_bot[rb][w][lane] = mu2[4];

            // Pairwise sync with vertical neighbor warps (lower id first).
            // Chain is acyclic -> deadlock-free; BAR.SYNC drains the STS.
            if (w > 0)  asm volatile("bar.sync %0, 64;" :: "r"(w)     : "memory");
            if (w < 15) asm volatile("bar.sync %0, 64;" :: "r"(w + 1) : "memory");

            const ull nb_above = (w > 0)  ? s_bot[rb][w - 1][lane] : mu2[0];
            const ull nb_below = (w < 15) ? s_top[rb][w + 1][lane] : mu2[4];

            ull above = nb_above;
            #pragma unroll
            for (int r = 0; r < 5; ++r) {
                const ull cur   = mu2[r];
                const ull below = (r < 4) ? mu2[r + 1] : nb_below;   // old values
                const ull czr   = (r == 0) ? cz0_2 : cx2[r - 1];
                float clo, chi; upk(cur, clo, chi);
                const float phi = __shfl_up_sync(0xFFFFFFFFu, chi, 1);
                const float nlo = __shfl_down_sync(0xFFFFFFFFu, clo, 1);

                ull dmu = fma2(ax2[r], cur, ay2[r]);
                dmu = fma2(cx2[r], below, dmu);
                dmu = fma2(cy2[r], pk(chi, nlo), dmu);
                dmu = fma2(czr,   above, dmu);
                dmu = fma2(cw2[r], pk(phi, clo), dmu);

                v2[r] = fma2(K07, v2[r], dmu);
                above = cur;
                mu2[r] = clip2(add2(cur, v2[r]));
            }
        }

        const int d = (per + 1) & 1;

        // Write exact interior: region rows 8..71, lanes 8..23 (cols 16..47).
        if (lane >= 8 && lane < 24) {
            #pragma unroll
            for (int r = 0; r < 5; ++r) {
                const int R = w * 5 + r;
                if (R >= 8 && R < 72) {
                    const int p0 = base + (((r0 + r) & 255) << 8) + gc0;
                    *(ull*)&g_mu[d][p0] = mu2[r];
                    *(ull*)&g_v [d][p0] = v2[r];
                    if (per == 12) *(ull*)&out[p0] = mu2[r];
                }
            }
        }

        if (per == 12) break;

        // ---- sense-reversing global period barrier ----
        __threadfence();
        __syncthreads();
        if (threadIdx.x == 0) {
            local_sense ^= 1u;
            const unsigned t = atomicAdd(&g_count, 1u);
            if (t == NBLOCKS - 1) {
                g_count = 0u;                 // reset BEFORE publishing sense
                __threadfence();
                g_sense = local_sense;
            } else {
                while (g_sense != local_sense) { }
            }
            __threadfence();
        }
        __syncthreads();

        // Reload halo cells' mu,v (interior stays in registers).
        #pragma unroll
        for (int r = 0; r < 5; ++r) {
            const int R = w * 5 + r;
            const bool interior = (R >= 8) && (R < 72) && (lane >= 8) && (lane < 24);
            if (!interior) {
                const int p0 = base + (((r0 + r) & 255) << 8) + gc0;
                mu2[r] = *(const ull*)&g_mu[d][p0];
                v2[r]  = *(const ull*)&g_v[d][p0];
            }
        }
    }
}

// ---------------- launch: single persistent kernel ----------------
extern "C" void kernel_launch(void* const* d_in, const int* in_sizes, int n_in,
                              void* d_out, int out_size) {
    const float*  y   = (const float*)d_in[0];
    const float2* ew2 = (const float2*)d_in[1];
    const float2* un2 = (const float2*)d_in[2];
    float* out = (float*)d_out;

    persist_kernel<<<NBLOCKS, 512>>>(y, ew2, un2, out);
}

// round 14
// speedup vs baseline: 1.2060x; 1.1063x over previous
#include <cuda_runtime.h>
#include <cstdint>

// B=4, H=256, W=256 torus. mu-subsystem only. Persistent kernel:
// f32x2 packed (lane = column pair). 128 blocks (1/SM) x 1024 thr;
// 32 warps x (3 rows x 64 cols). Region 96r x 64c, interior 64r x 32c,
// T=16, 7 periods (6x16 + 4). One block-wide sync per iteration;
// 8 warps/SMSP for latency hiding. Separate coalesced init kernel (proven).
#define BHW 262144
#define NBLOCKS 128

typedef unsigned long long ull;

__device__ float  g_mu[2][BHW];
__device__ float  g_v [2][BHW];
__device__ float4 g_c [BHW];          // 0.01*(ex, ey, eu0, el1)
__device__ float2 g_ac[BHW];          // 0.01*(2*uw1, uw2*y)
__device__ unsigned g_bar;            // reset by init kernel each replay

// ---------------- packed f32x2 helpers ----------------
__device__ __forceinline__ ull pk(float lo, float hi) {
    ull r; asm("mov.b64 %0, {%1, %2};" : "=l"(r) : "f"(lo), "f"(hi)); return r;
}
__device__ __forceinline__ void upk(ull a, float& lo, float& hi) {
    asm("mov.b64 {%0, %1}, %2;" : "=f"(lo), "=f"(hi) : "l"(a));
}
__device__ __forceinline__ ull fma2(ull a, ull b, ull c) {
    ull d; asm("fma.rn.f32x2 %0, %1, %2, %3;" : "=l"(d) : "l"(a), "l"(b), "l"(c)); return d;
}
__device__ __forceinline__ ull add2(ull a, ull b) {
    ull d; asm("add.rn.f32x2 %0, %1, %2;" : "=l"(d) : "l"(a), "l"(b)); return d;
}
__device__ __forceinline__ ull clip2(ull a) {
    float lo, hi; upk(a, lo, hi);
    lo = fminf(fmaxf(lo, 0.0f), 63.0f);
    hi = fminf(fmaxf(hi, 0.0f), 63.0f);
    return pk(lo, hi);
}

#define K07 0x3F3333333F333333ULL   // (0.7f, 0.7f)

// ---------------- init: pack per-pixel constants (coalesced, 1024 blocks) --
__global__ __launch_bounds__(256) void init_kernel(const float* __restrict__ y,
                                                   const float2* __restrict__ ew2,
                                                   const float2* __restrict__ un2) {
    const int p = blockIdx.x * 256 + threadIdx.x;
    const int base = p & ~65535;
    const int i    = p &  65535;
    const int row  = i & ~255;
    const int pu = base | ((i + 65280) & 65535);
    const int pl = base | row | ((i + 255) & 255);

    const float yv = y[p];
    const float2 e  = ew2[p];
    const float  eu = ew2[pu].x;
    const float  el = ew2[pl].y;
    const float2 u  = un2[p];

    g_mu[0][p] = yv;
    g_v [0][p] = 0.0f;
    g_c [p]    = make_float4(0.01f * e.x, 0.01f * e.y, 0.01f * eu, 0.01f * el);
    g_ac[p]    = make_float2(0.01f * 2.0f * u.x, 0.01f * u.y * yv);
    if (p == 0) g_bar = 0u;
}

// ---------------- persistent kernel ----------------
__global__ __launch_bounds__(1024, 1) void persist_kernel(float* __restrict__ out) {
    __shared__ ull s_top[2][32][32];     // warp row-0 mu pairs, double-buffered
    __shared__ ull s_bot[2][32][32];     // warp row-2 mu pairs

    const int lane = threadIdx.x & 31;
    const int w    = threadIdx.x >> 5;            // band 0..31 (3 rows each)
    const int blk  = blockIdx.x;                  // 4 img x 4 vtile x 8 htile
    const int base = (blk >> 5) << 16;
    const int tv   = (blk >> 3) & 3;
    const int th   = blk & 7;
    const int gc0  = (th * 32 - 16 + 2 * lane) & 255;   // even; pair never wraps
    const int r0   = tv * 64 - 16 + w * 3;              // region row origin

    // Packed per-row state. cz2[r] == cx2[r-1]; row 0 needs explicit cz0_2.
    ull mu2[3], v2[3], cx2[3], cy2[3], cw2[3], ax2[3], ay2[3], cz0_2;

    #pragma unroll
    for (int r = 0; r < 3; ++r) {
        const int p0 = base + (((r0 + r) & 255) << 8) + gc0;
        mu2[r] = *(const ull*)&g_mu[0][p0];
        v2[r]  = *(const ull*)&g_v[0][p0];
        const float4 c0 = g_c[p0], c1 = g_c[p0 + 1];
        cx2[r] = pk(c0.x, c1.x);
        cy2[r] = pk(c0.y, c1.y);
        cw2[r] = pk(c0.w, c1.w);
        const float2 a0 = g_ac[p0], a1 = g_ac[p0 + 1];
        ax2[r] = pk(a0.x, a1.x);
        ay2[r] = pk(a0.y, a1.y);
    }
    {
        const int pu = base + (((r0 + 255) & 255) << 8) + gc0;
        const float4 cu0 = g_c[pu], cu1 = g_c[pu + 1];
        cz0_2 = pk(cu0.x, cu1.x);
    }
    __syncthreads();

    unsigned target = 0;

    for (int per = 0; per < 7; ++per) {
        const int TT = (per < 6) ? 16 : 4;

        #pragma unroll 2
        for (int it = 0; it < TT; ++it) {
            const int rb = it & 1;

            // Publish own old boundary rows; one block sync per iteration.
            s_top[rb][w][lane] = mu2[0];
            s_bot[rb][w][lane] = mu2[2];
            __syncthreads();

            const ull nb_above = (w > 0)  ? s_bot[rb][w - 1][lane] : mu2[0];
            const ull nb_below = (w < 31) ? s_top[rb][w + 1][lane] : mu2[2];

            ull above = nb_above;
            #pragma unroll
            for (int r = 0; r < 3; ++r) {
                const ull cur   = mu2[r];
                const ull below = (r < 2) ? mu2[r + 1] : nb_below;   // old values
                const ull czr   = (r == 0) ? cz0_2 : cx2[r - 1];
                float clo, chi; upk(cur, clo, chi);
                const float phi = __shfl_up_sync(0xFFFFFFFFu, chi, 1);
                const float nlo = __shfl_down_sync(0xFFFFFFFFu, clo, 1);

                ull dmu = fma2(ax2[r], cur, ay2[r]);
                dmu = fma2(cx2[r], below, dmu);
                dmu = fma2(cy2[r], pk(chi, nlo), dmu);
                dmu = fma2(czr,   above, dmu);
                dmu = fma2(cw2[r], pk(phi, clo), dmu);

                v2[r] = fma2(K07, v2[r], dmu);
                above = cur;
                mu2[r] = clip2(add2(cur, v2[r]));
            }
        }

        const int d = (per + 1) & 1;

        // Write exact interior: region rows 16..79, lanes 8..23 (cols 16..47).
        if (lane >= 8 && lane < 24) {
            #pragma unroll
            for (int r = 0; r < 3; ++r) {
                const int R = w * 3 + r;
                if (R >= 16 && R < 80) {
                    const int p0 = base + (((r0 + r) & 255) << 8) + gc0;
                    *(ull*)&g_mu[d][p0] = mu2[r];
                    *(ull*)&g_v [d][p0] = v2[r];
                    if (per == 6) *(ull*)&out[p0] = mu2[r];
                }
            }
        }

        if (per == 6) break;

        // ---- global period barrier (single counter, proven) ----
        __threadfence();
        __syncthreads();
        target += NBLOCKS;
        if (threadIdx.x == 0) {
            atomicAdd(&g_bar, 1u);
            while (*((volatile unsigned*)&g_bar) < target) { }
            __threadfence();
        }
        __syncthreads();

        // Reload halo cells' mu,v (interior stays in registers).
        #pragma unroll
        for (int r = 0; r < 3; ++r) {
            const int R = w * 3 + r;
            const bool interior = (R >= 16) && (R < 80) && (lane >= 8) && (lane < 24);
            if (!interior) {
                const int p0 = base + (((r0 + r) & 255) << 8) + gc0;
                mu2[r] = *(const ull*)&g_mu[d][p0];
                v2[r]  = *(const ull*)&g_v[d][p0];
            }
        }
    }
}

// ---------------- launch ----------------
extern "C" void kernel_launch(void* const* d_in, const int* in_sizes, int n_in,
                              void* d_out, int out_size) {
    const float* y  = (const float*)d_in[0];
    const float* ew = (const float*)d_in[1];
    const float* un = (const float*)d_in[2];
    float* out = (float*)d_out;

    init_kernel<<<1024, 256>>>(y, (const float2*)ew, (const float2*)un);
    persist_kernel<<<NBLOCKS, 1024>>>(out);
}

// round 15
// speedup vs baseline: 1.3258x; 1.0993x over previous
#include <cuda_runtime.h>
#include <cstdint>

// B=4, H=256, W=256 torus. mu-subsystem only. Persistent kernel:
// f32x2 packed (lane = column pair). 128 blocks (1/SM) x 1024 thr;
// 32 warps x (3 rows x 64 cols). Region 96r x 64c, interior 64r x 32c,
// T=16, 7 periods (6x16 + 4). Fully unrolled iteration bodies,
// pre-clamped neighbor addresses, one block sync per iteration.
#define BHW 262144
#define NBLOCKS 128

typedef unsigned long long ull;

__device__ float  g_mu[2][BHW];
__device__ float  g_v [2][BHW];
__device__ float4 g_c [BHW];          // 0.01*(ex, ey, eu0, el1)
__device__ float2 g_ac[BHW];          // 0.01*(2*uw1, uw2*y)
__device__ unsigned g_bar;            // reset by init kernel each replay

// ---------------- packed f32x2 helpers ----------------
__device__ __forceinline__ ull pk(float lo, float hi) {
    ull r; asm("mov.b64 %0, {%1, %2};" : "=l"(r) : "f"(lo), "f"(hi)); return r;
}
__device__ __forceinline__ void upk(ull a, float& lo, float& hi) {
    asm("mov.b64 {%0, %1}, %2;" : "=f"(lo), "=f"(hi) : "l"(a));
}
__device__ __forceinline__ ull fma2(ull a, ull b, ull c) {
    ull d; asm("fma.rn.f32x2 %0, %1, %2, %3;" : "=l"(d) : "l"(a), "l"(b), "l"(c)); return d;
}
__device__ __forceinline__ ull add2(ull a, ull b) {
    ull d; asm("add.rn.f32x2 %0, %1, %2;" : "=l"(d) : "l"(a), "l"(b)); return d;
}
__device__ __forceinline__ ull clip2(ull a) {
    float lo, hi; upk(a, lo, hi);
    lo = fminf(fmaxf(lo, 0.0f), 63.0f);
    hi = fminf(fmaxf(hi, 0.0f), 63.0f);
    return pk(lo, hi);
}

#define K07 0x3F3333333F333333ULL   // (0.7f, 0.7f)

// ---------------- init: pack per-pixel constants (coalesced) ----------------
__global__ __launch_bounds__(256) void init_kernel(const float* __restrict__ y,
                                                   const float2* __restrict__ ew2,
                                                   const float2* __restrict__ un2) {
    const int p = blockIdx.x * 256 + threadIdx.x;
    const int base = p & ~65535;
    const int i    = p &  65535;
    const int row  = i & ~255;
    const int pu = base | ((i + 65280) & 65535);
    const int pl = base | row | ((i + 255) & 255);

    const float yv = y[p];
    const float2 e  = ew2[p];
    const float  eu = ew2[pu].x;
    const float  el = ew2[pl].y;
    const float2 u  = un2[p];

    g_mu[0][p] = yv;
    g_v [0][p] = 0.0f;
    g_c [p]    = make_float4(0.01f * e.x, 0.01f * e.y, 0.01f * eu, 0.01f * el);
    g_ac[p]    = make_float2(0.01f * 2.0f * u.x, 0.01f * u.y * yv);
    if (p == 0) g_bar = 0u;
}

// ---------------- unrolled iteration body ----------------
// smem layout: s[buf][kind][warp][lane], kind 0 = top(row0), 1 = bot(row2)
template<int TT>
__device__ __forceinline__ void do_iters(
        ull (&mu2)[3], ull (&v2)[3],
        const ull (&cx2)[3], const ull (&cy2)[3], const ull (&cw2)[3],
        const ull (&ax2)[3], const ull (&ay2)[3], const ull cz0_2,
        ull* __restrict__ sm,             // &s[0][0][0][0]
        const int w, const int lane, const int wm1, const int wp1) {
    #pragma unroll
    for (int it = 0; it < TT; ++it) {
        const int rb = it & 1;            // compile-time after unroll
        ull* buf = sm + rb * 2048;        // [2][32][32] per buffer

        // Publish own old boundary rows; one block sync per iteration.
        buf[w * 32 + lane]        = mu2[0];          // top
        buf[1024 + w * 32 + lane] = mu2[2];          // bot
        __syncthreads();

        // Pre-clamped indices: w==0 / w==31 read garbage-but-finite halo
        // values (region edge rows are halo; contamination covered by T).
        const ull nb_above = buf[1024 + wm1 * 32 + lane];
        const ull nb_below = buf[wp1 * 32 + lane];

        ull above = nb_above;
        #pragma unroll
        for (int r = 0; r < 3; ++r) {
            const ull cur   = mu2[r];
            const ull below = (r < 2) ? mu2[r + 1] : nb_below;   // old values
            const ull czr   = (r == 0) ? cz0_2 : cx2[r - 1];
            float clo, chi; upk(cur, clo, chi);
            const float phi = __shfl_up_sync(0xFFFFFFFFu, chi, 1);
            const float nlo = __shfl_down_sync(0xFFFFFFFFu, clo, 1);

            ull dmu = fma2(ax2[r], cur, ay2[r]);
            dmu = fma2(cx2[r], below, dmu);
            dmu = fma2(cy2[r], pk(chi, nlo), dmu);
            dmu = fma2(czr,   above, dmu);
            dmu = fma2(cw2[r], pk(phi, clo), dmu);

            v2[r] = fma2(K07, v2[r], dmu);
            above = cur;
            mu2[r] = clip2(add2(cur, v2[r]));
        }
    }
}

// ---------------- persistent kernel ----------------
__global__ __launch_bounds__(1024, 1) void persist_kernel(float* __restrict__ out) {
    __shared__ ull s_bufs[2][2][32][32];     // [buf][top/bot][warp][lane]

    const int lane = threadIdx.x & 31;
    const int w    = threadIdx.x >> 5;            // band 0..31 (3 rows each)
    const int wm1  = (w > 0)  ? w - 1 : w;
    const int wp1  = (w < 31) ? w + 1 : w;
    const int blk  = blockIdx.x;                  // 4 img x 4 vtile x 8 htile
    const int base = (blk >> 5) << 16;
    const int tv   = (blk >> 3) & 3;
    const int th   = blk & 7;
    const int gc0  = (th * 32 - 16 + 2 * lane) & 255;   // even; pair never wraps
    const int r0   = tv * 64 - 16 + w * 3;              // region row origin

    ull* sm = &s_bufs[0][0][0][0];

    // Packed per-row state. cz2[r] == cx2[r-1]; row 0 needs explicit cz0_2.
    ull mu2[3], v2[3], cx2[3], cy2[3], cw2[3], ax2[3], ay2[3], cz0_2;

    // Period-invariant global addresses (per row).
    int paddr[3];
    #pragma unroll
    for (int r = 0; r < 3; ++r)
        paddr[r] = base + (((r0 + r) & 255) << 8) + gc0;

    #pragma unroll
    for (int r = 0; r < 3; ++r) {
        const int p0 = paddr[r];
        mu2[r] = *(const ull*)&g_mu[0][p0];
        v2[r]  = *(const ull*)&g_v[0][p0];
        const float4 c0 = g_c[p0], c1 = g_c[p0 + 1];
        cx2[r] = pk(c0.x, c1.x);
        cy2[r] = pk(c0.y, c1.y);
        cw2[r] = pk(c0.w, c1.w);
        const float2 a0 = g_ac[p0], a1 = g_ac[p0 + 1];
        ax2[r] = pk(a0.x, a1.x);
        ay2[r] = pk(a0.y, a1.y);
    }
    {
        const int pu = base + (((r0 + 255) & 255) << 8) + gc0;
        const float4 cu0 = g_c[pu], cu1 = g_c[pu + 1];
        cz0_2 = pk(cu0.x, cu1.x);
    }
    __syncthreads();

    const int R = w * 3;                         // first region row of band
    const bool wr_lane = (lane >= 8) && (lane < 24);
    unsigned target = 0;

    for (int per = 0; per < 7; ++per) {
        if (per < 6)
            do_iters<16>(mu2, v2, cx2, cy2, cw2, ax2, ay2, cz0_2, sm, w, lane, wm1, wp1);
        else
            do_iters<4>(mu2, v2, cx2, cy2, cw2, ax2, ay2, cz0_2, sm, w, lane, wm1, wp1);

        const int d = (per + 1) & 1;

        // Write exact interior: region rows 16..79, lanes 8..23 (cols 16..47).
        if (wr_lane) {
            #pragma unroll
            for (int r = 0; r < 3; ++r) {
                if (R + r >= 16 && R + r < 80) {
                    const int p0 = paddr[r];
                    *(ull*)&g_mu[d][p0] = mu2[r];
                    *(ull*)&g_v [d][p0] = v2[r];
                    if (per == 6) *(ull*)&out[p0] = mu2[r];
                }
            }
        }

        if (per == 6) break;

        // ---- global period barrier (single counter, proven) ----
        __threadfence();
        __syncthreads();
        target += NBLOCKS;
        if (threadIdx.x == 0) {
            atomicAdd(&g_bar, 1u);
            while (*((volatile unsigned*)&g_bar) < target) { }
            __threadfence();
        }
        __syncthreads();

        // Reload halo cells' mu,v (interior stays in registers).
        #pragma unroll
        for (int r = 0; r < 3; ++r) {
            const bool interior = (R + r >= 16) && (R + r < 80) && wr_lane;
            if (!interior) {
                const int p0 = paddr[r];
                mu2[r] = *(const ull*)&g_mu[d][p0];
                v2[r]  = *(const ull*)&g_v[d][p0];
            }
        }
    }
}

// ---------------- launch ----------------
extern "C" void kernel_launch(void* const* d_in, const int* in_sizes, int n_in,
                              void* d_out, int out_size) {
    const float* y  = (const float*)d_in[0];
    const float* ew = (const float*)d_in[1];
    const float* un = (const float*)d_in[2];
    float* out = (float*)d_out;

    init_kernel<<<1024, 256>>>(y, (const float2*)ew, (const float2*)un);
    persist_kernel<<<NBLOCKS, 1024>>>(out);
}

// round 17
// speedup vs baseline: 1.3299x; 1.0031x over previous
#include <cuda_runtime.h>
#include <cstdint>

// B=4, H=256, W=256 torus. mu-subsystem only. Persistent kernel:
// f32x2 packed (lane = column pair). 128 blocks (1/SM) x 1024 thr;
// 32 warps x (3 rows x 64 cols). Region 96r x 64c, interior 64r x 32c,
// T=16, 7 periods (6x16 + 4). Fully unrolled; row 1 (neighbor-independent)
// computed BEFORE the per-iteration barrier to hide BAR latency.
#define BHW 262144
#define NBLOCKS 128

typedef unsigned long long ull;

__device__ float  g_mu[2][BHW];
__device__ float  g_v [2][BHW];
__device__ float4 g_c [BHW];          // 0.01*(ex, ey, eu0, el1)
__device__ float2 g_ac[BHW];          // 0.01*(2*uw1, uw2*y)
__device__ unsigned g_bar;            // reset by init kernel each replay

// ---------------- packed f32x2 helpers ----------------
__device__ __forceinline__ ull pk(float lo, float hi) {
    ull r; asm("mov.b64 %0, {%1, %2};" : "=l"(r) : "f"(lo), "f"(hi)); return r;
}
__device__ __forceinline__ void upk(ull a, float& lo, float& hi) {
    asm("mov.b64 {%0, %1}, %2;" : "=f"(lo), "=f"(hi) : "l"(a));
}
__device__ __forceinline__ ull fma2(ull a, ull b, ull c) {
    ull d; asm("fma.rn.f32x2 %0, %1, %2, %3;" : "=l"(d) : "l"(a), "l"(b), "l"(c)); return d;
}
__device__ __forceinline__ ull add2(ull a, ull b) {
    ull d; asm("add.rn.f32x2 %0, %1, %2;" : "=l"(d) : "l"(a), "l"(b)); return d;
}
__device__ __forceinline__ ull clip2(ull a) {
    float lo, hi; upk(a, lo, hi);
    lo = fminf(fmaxf(lo, 0.0f), 63.0f);
    hi = fminf(fmaxf(hi, 0.0f), 63.0f);
    return pk(lo, hi);
}

#define K07 0x3F3333333F333333ULL   // (0.7f, 0.7f)

// ---------------- init: pack per-pixel constants (coalesced) ----------------
__global__ __launch_bounds__(256) void init_kernel(const float* __restrict__ y,
                                                   const float2* __restrict__ ew2,
                                                   const float2* __restrict__ un2) {
    const int p = blockIdx.x * 256 + threadIdx.x;
    const int base = p & ~65535;
    const int i    = p &  65535;
    const int row  = i & ~255;
    const int pu = base | ((i + 65280) & 65535);
    const int pl = base | row | ((i + 255) & 255);

    const float yv = y[p];
    const float2 e  = ew2[p];
    const float  eu = ew2[pu].x;
    const float  el = ew2[pl].y;
    const float2 u  = un2[p];

    g_mu[0][p] = yv;
    g_v [0][p] = 0.0f;
    g_c [p]    = make_float4(0.01f * e.x, 0.01f * e.y, 0.01f * eu, 0.01f * el);
    g_ac[p]    = make_float2(0.01f * 2.0f * u.x, 0.01f * u.y * yv);
    if (p == 0) g_bar = 0u;
}

// ---------------- unrolled iteration body ----------------
// smem: sm[buf*2048 + kind*1024 + w*32 + lane], kind 0 = top(row0), 1 = bot(row2)
template<int TT>
__device__ __forceinline__ void do_iters(
        ull (&mu2)[3], ull (&v2)[3],
        const ull (&cx2)[3], const ull (&cy2)[3], const ull (&cw2)[3],
        const ull (&ax2)[3], const ull (&ay2)[3], const ull cz0_2,
        ull* __restrict__ sm,
        const int w, const int lane, const int wm1, const int wp1) {
    #pragma unroll
    for (int it = 0; it < TT; ++it) {
        const int rb = it & 1;            // compile-time after unroll
        ull* buf = sm + rb * 2048;

        // Publish own old boundary rows.
        buf[w * 32 + lane]        = mu2[0];          // top
        buf[1024 + w * 32 + lane] = mu2[2];          // bot

        // ---- row 1: neighbor-independent; computed BEFORE the barrier ----
        const ull old1 = mu2[1];
        {
            float clo, chi; upk(old1, clo, chi);
            const float phi = __shfl_up_sync(0xFFFFFFFFu, chi, 1);
            const float nlo = __shfl_down_sync(0xFFFFFFFFu, clo, 1);
            ull dmu = fma2(ax2[1], old1, ay2[1]);
            dmu = fma2(cx2[1], mu2[2], dmu);            // below (old)
            dmu = fma2(cy2[1], pk(chi, nlo), dmu);      // right
            dmu = fma2(cx2[0], mu2[0], dmu);            // above (old)
            dmu = fma2(cw2[1], pk(phi, clo), dmu);      // left
            v2[1] = fma2(K07, v2[1], dmu);
            mu2[1] = clip2(add2(old1, v2[1]));
        }

        __syncthreads();

        const ull nb_above = buf[1024 + wm1 * 32 + lane];
        const ull nb_below = buf[wp1 * 32 + lane];

        // ---- row 0 ----
        {
            const ull cur = mu2[0];
            float clo, chi; upk(cur, clo, chi);
            const float phi = __shfl_up_sync(0xFFFFFFFFu, chi, 1);
            const float nlo = __shfl_down_sync(0xFFFFFFFFu, clo, 1);
            ull dmu = fma2(ax2[0], cur, ay2[0]);
            dmu = fma2(cx2[0], old1, dmu);              // below = old row1
            dmu = fma2(cy2[0], pk(chi, nlo), dmu);
            dmu = fma2(cz0_2,  nb_above, dmu);
            dmu = fma2(cw2[0], pk(phi, clo), dmu);
            v2[0] = fma2(K07, v2[0], dmu);
            mu2[0] = clip2(add2(cur, v2[0]));
        }
        // ---- row 2 ----
        {
            const ull cur = mu2[2];
            float clo, chi; upk(cur, clo, chi);
            const float phi = __shfl_up_sync(0xFFFFFFFFu, chi, 1);
            const float nlo = __shfl_down_sync(0xFFFFFFFFu, clo, 1);
            ull dmu = fma2(ax2[2], cur, ay2[2]);
            dmu = fma2(cx2[2], nb_below, dmu);
            dmu = fma2(cy2[2], pk(chi, nlo), dmu);
            dmu = fma2(cx2[1], old1, dmu);              // above = old row1
            dmu = fma2(cw2[2], pk(phi, clo), dmu);
            v2[2] = fma2(K07, v2[2], dmu);
            mu2[2] = clip2(add2(cur, v2[2]));
        }
    }
}

// ---------------- persistent kernel ----------------
__global__ __launch_bounds__(1024, 1) void persist_kernel(float* __restrict__ out) {
    __shared__ ull s_bufs[2][2][32][32];     // [buf][top/bot][warp][lane]

    const int lane = threadIdx.x & 31;
    const int w    = threadIdx.x >> 5;            // band 0..31 (3 rows each)
    const int wm1  = (w > 0)  ? w - 1 : w;
    const int wp1  = (w < 31) ? w + 1 : w;
    const int blk  = blockIdx.x;                  // 4 img x 4 vtile x 8 htile
    const int base = (blk >> 5) << 16;
    const int tv   = (blk >> 3) & 3;
    const int th   = blk & 7;
    const int gc0  = (th * 32 - 16 + 2 * lane) & 255;   // even; pair never wraps
    const int r0   = tv * 64 - 16 + w * 3;              // region row origin

    ull* sm = &s_bufs[0][0][0][0];

    ull mu2[3], v2[3], cx2[3], cy2[3], cw2[3], ax2[3], ay2[3], cz0_2;

    int paddr[3];
    #pragma unroll
    for (int r = 0; r < 3; ++r)
        paddr[r] = base + (((r0 + r) & 255) << 8) + gc0;

    #pragma unroll
    for (int r = 0; r < 3; ++r) {
        const int p0 = paddr[r];
        mu2[r] = *(const ull*)&g_mu[0][p0];
        v2[r]  = *(const ull*)&g_v[0][p0];
        const float4 c0 = g_c[p0], c1 = g_c[p0 + 1];
        cx2[r] = pk(c0.x, c1.x);
        cy2[r] = pk(c0.y, c1.y);
        cw2[r] = pk(c0.w, c1.w);
        const float2 a0 = g_ac[p0], a1 = g_ac[p0 + 1];
        ax2[r] = pk(a0.x, a1.x);
        ay2[r] = pk(a0.y, a1.y);
    }
    {
        const int pu = base + (((r0 + 255) & 255) << 8) + gc0;
        const float4 cu0 = g_c[pu], cu1 = g_c[pu + 1];
        cz0_2 = pk(cu0.x, cu1.x);
    }
    __syncthreads();

    const int R = w * 3;
    const bool wr_lane = (lane >= 8) && (lane < 24);
    unsigned target = 0;

    for (int per = 0; per < 7; ++per) {
        if (per < 6)
            do_iters<16>(mu2, v2, cx2, cy2, cw2, ax2, ay2, cz0_2, sm, w, lane, wm1, wp1);
        else
            do_iters<4>(mu2, v2, cx2, cy2, cw2, ax2, ay2, cz0_2, sm, w, lane, wm1, wp1);

        const int d = (per + 1) & 1;

        // Write exact interior: region rows 16..79, lanes 8..23 (cols 16..47).
        if (wr_lane) {
            #pragma unroll
            for (int r = 0; r < 3; ++r) {
                if (R + r >= 16 && R + r < 80) {
                    const int p0 = paddr[r];
                    *(ull*)&g_mu[d][p0] = mu2[r];
                    *(ull*)&g_v [d][p0] = v2[r];
                    if (per == 6) *(ull*)&out[p0] = mu2[r];
                }
            }
        }

        if (per == 6) break;

        // ---- global period barrier (single counter, proven) ----
        __threadfence();
        __syncthreads();
        target += NBLOCKS;
        if (threadIdx.x == 0) {
            atomicAdd(&g_bar, 1u);
            while (*((volatile unsigned*)&g_bar) < target) { }
            __threadfence();
        }
        __syncthreads();

        // Reload halo cells' mu,v (interior stays in registers).
        #pragma unroll
        for (int r = 0; r < 3; ++r) {
            const bool interior = (R + r >= 16) && (R + r < 80) && wr_lane;
            if (!interior) {
                const int p0 = paddr[r];
                mu2[r] = *(const ull*)&g_mu[d][p0];
                v2[r]  = *(const ull*)&g_v[d][p0];
            }
        }
    }
}

// ---------------- launch ----------------
extern "C" void kernel_launch(void* const* d_in, const int* in_sizes, int n_in,
                              void* d_out, int out_size) {
    const float* y  = (const float*)d_in[0];
    const float* ew = (const float*)d_in[1];
    const float* un = (const float*)d_in[2];
    float* out = (float*)d_out;

    init_kernel<<<1024, 256>>>(y, (const float2*)ew, (const float2*)un);
    persist_kernel<<<NBLOCKS, 1024>>>(out);
}